// round 13
// baseline (speedup 1.0000x reference)
#include <cuda_runtime.h>
#include <cuda_fp16.h>
#include <math_constants.h>

typedef unsigned int u32;

// Problem: inputs [64,32,32,64] f32 -> N=65536 rows, D=64; embeddings [64,512] f32.
// Output (f32 concat): quantized [N*64] | indices [N] | loss [1]
#define N_ROWS   65536
#define DIM      64
#define KCODES   512
#define ROWS_BLK 256
#define THREADS  512
#define NCTAS    (N_ROWS / ROWS_BLK)     // 256 CTAs, single wave

#define Q_ELEMS  ((size_t)N_ROWS * DIM)
#define IDX_OFF  Q_ELEMS
#define LOSS_OFF (Q_ELEMS + N_ROWS)

// SMEM layout (bytes)
#define ASTRIDE   144                    // A: 128B fp16 row + 16B pad
#define BSTRIDE   144                    // B: [code][d] 128B row + 16B pad
#define OFF_A     0                                   // 256*144 = 36864
#define OFF_B     (OFF_A + ROWS_BLK * ASTRIDE)        // 36864
#define OFF_ENORM (OFF_B + KCODES * BSTRIDE)          // 110592
#define SMEM_TOTAL (OFF_ENORM + KCODES * 4)           // 112640 -> 2 CTAs/SM
// post-mainloop overlays inside dead A region:
#define OFF_FLAGC   0
#define OFF_FLAGL   16
#define OFF_ROWCODE 2048
#define OFF_RED     4096

// fp16 flip band ~0.075 worst-case + packing 0.001 -> 0.09 is rigorous.
#define BAND_T 0.09f

__device__ float  g_partials[NCTAS];
__device__ int    g_done = 0;
__device__ __half g_B2h[KCODES * DIM];   // fp16 (-2*E), [code][d]
__device__ float  g_ET[KCODES * DIM];    // fp32 E transposed, [code][d]
__device__ float  g_enorm[KCODES];

// ---------------------------------------------------------------------------
static __device__ __forceinline__ u32 smem_u32(const void* p) {
    u32 a;
    asm("{ .reg .u64 t; cvta.to.shared.u64 t, %1; cvt.u32.u64 %0, t; }" : "=r"(a) : "l"(p));
    return a;
}
static __device__ __forceinline__ void ldsm_x4(u32& r0, u32& r1, u32& r2, u32& r3, u32 a) {
    asm volatile("ldmatrix.sync.aligned.m8n8.x4.shared.b16 {%0,%1,%2,%3}, [%4];"
                 : "=r"(r0), "=r"(r1), "=r"(r2), "=r"(r3) : "r"(a));
}
static __device__ __forceinline__ void mma_f16(float* c, const u32* a, u32 b0, u32 b1) {
    asm volatile("mma.sync.aligned.m16n8k16.row.col.f32.f16.f16.f32 "
                 "{%0,%1,%2,%3}, {%4,%5,%6,%7}, {%8,%9}, {%0,%1,%2,%3};"
                 : "+f"(c[0]), "+f"(c[1]), "+f"(c[2]), "+f"(c[3])
                 : "r"(a[0]), "r"(a[1]), "r"(a[2]), "r"(a[3]), "r"(b0), "r"(b1));
}
static __device__ __forceinline__ void mma_f16_init(float* d, const u32* a, u32 b0, u32 b1,
                                                    float e0, float e1) {
    asm volatile("mma.sync.aligned.m16n8k16.row.col.f32.f16.f16.f32 "
                 "{%0,%1,%2,%3}, {%4,%5,%6,%7}, {%8,%9}, {%10,%11,%10,%11};"
                 : "=f"(d[0]), "=f"(d[1]), "=f"(d[2]), "=f"(d[3])
                 : "r"(a[0]), "r"(a[1]), "r"(a[2]), "r"(a[3]), "r"(b0), "r"(b1),
                   "f"(e0), "f"(e1));
}
// pack code into low 9 mantissa bits (|dist_rel|<16 -> pack error < 1e-3)
static __device__ __forceinline__ float packkey(float v, int code) {
    return __uint_as_float((__float_as_uint(v) & 0xFFFFFE00u) | (u32)code);
}

// ---------------------------------------------------------------------------
// Kernel 1: prep — fp16 (-2E) [code][d], fp32 E^T, enorm
// ---------------------------------------------------------------------------
__global__ void vq_prep_kernel(const float* __restrict__ E) {
    int gid = blockIdx.x * 512 + threadIdx.x;        // 0..32767 == d*512 + code
    float v = E[gid];
    int d = gid >> 9, c = gid & 511;
    g_B2h[c * DIM + d] = __float2half_rn(-2.f * v);
    g_ET[c * DIM + d]  = v;
    if (gid < KCODES) {
        float s = 0.f;
        #pragma unroll 16
        for (int dd = 0; dd < DIM; ++dd) {
            float e = E[(size_t)dd * KCODES + gid];
            s = fmaf(e, e, s);
        }
        g_enorm[gid] = s;
    }
}

// ---------------------------------------------------------------------------
// exact fp32 distances for two candidate codes of one row
// ---------------------------------------------------------------------------
static __device__ __forceinline__ void exact2(const float* __restrict__ X,
                                              const float* __restrict__ enorm_s,
                                              int row, int c1, int c2,
                                              float& d1, float& d2) {
    const float4* x4 = reinterpret_cast<const float4*>(X + (size_t)row * DIM);
    const float4* E1 = reinterpret_cast<const float4*>(g_ET + c1 * DIM);
    const float4* E2 = reinterpret_cast<const float4*>(g_ET + c2 * DIM);
    float s1 = 0.f, s2 = 0.f;
    #pragma unroll
    for (int i = 0; i < 16; ++i) {
        float4 xv = x4[i];
        float4 a  = E1[i];
        float4 b  = E2[i];
        s1 = fmaf(xv.x, a.x, s1); s1 = fmaf(xv.y, a.y, s1);
        s1 = fmaf(xv.z, a.z, s1); s1 = fmaf(xv.w, a.w, s1);
        s2 = fmaf(xv.x, b.x, s2); s2 = fmaf(xv.y, b.y, s2);
        s2 = fmaf(xv.z, b.z, s2); s2 = fmaf(xv.w, b.w, s2);
    }
    d1 = fmaf(-2.f, s1, enorm_s[c1]);
    d2 = fmaf(-2.f, s2, enorm_s[c2]);
}

// ---------------------------------------------------------------------------
// Kernel 2: main — fp16 GEMM mainloop + candidate-set exact refine
// ---------------------------------------------------------------------------
__global__ void __launch_bounds__(THREADS, 2)
vq_kernel(const float* __restrict__ X, const float* __restrict__ E,
          float* __restrict__ out, int out_size) {
    extern __shared__ char smem[];
    const u32 sb   = smem_u32(smem);
    const int tid  = threadIdx.x;
    const int lane = tid & 31;
    const int warp = tid >> 5;                // 0..15
    const int rowBase = blockIdx.x * ROWS_BLK;
    const int warpRow = warp * 16;

    float* enorm_s  = reinterpret_cast<float*>(smem + OFF_ENORM);
    int*   rowcode  = reinterpret_cast<int*>(smem + OFF_ROWCODE);
    int*   flagcnt  = reinterpret_cast<int*>(smem + OFF_FLAGC);
    int*   flaglist = reinterpret_cast<int*>(smem + OFF_FLAGL);

    // ---- A tile: fp32 -> fp16, [row][d] stride 144 ----
    #pragma unroll
    for (int it = 0; it < 4; ++it) {
        int task = tid + THREADS * it;        // 2048 tasks: 256 rows x 8 groups
        int r  = task >> 3;
        int d0 = (task & 7) * 8;
        const float4* xv = reinterpret_cast<const float4*>(
            X + (size_t)(rowBase + r) * DIM + d0);
        float4 v0 = xv[0], v1 = xv[1];
        float vals[8] = {v0.x, v0.y, v0.z, v0.w, v1.x, v1.y, v1.z, v1.w};
        union { __half h[8]; uint4 u; } ph;
        #pragma unroll
        for (int e = 0; e < 8; ++e) ph.h[e] = __float2half_rn(vals[e]);
        *reinterpret_cast<uint4*>(smem + OFF_A + r * ASTRIDE + d0 * 2) = ph.u;
    }
    // ---- B: copy -2E fp16 [code][d] rows (stride 144) ----
    {
        const uint4* src = reinterpret_cast<const uint4*>(g_B2h);
        #pragma unroll
        for (int it = 0; it < 8; ++it) {
            int i = tid + THREADS * it;       // 4096 uint4: 512 codes x 8 groups
            int c = i >> 3, q = i & 7;
            *reinterpret_cast<uint4*>(smem + OFF_B + c * BSTRIDE + q * 16) = src[i];
        }
    }
    enorm_s[tid] = g_enorm[tid];
    __syncthreads();

    // ---- hoisted A fragments ----
    const int mA = lane >> 3, rA8 = lane & 7;
    const u32 aBase = sb + OFF_A + (u32)((warpRow + (mA & 1) * 8 + rA8) * ASTRIDE
                                         + (mA >> 1) * 16);
    u32 af[4][4];
    #pragma unroll
    for (int ks = 0; ks < 4; ++ks)
        ldsm_x4(af[ks][0], af[ks][1], af[ks][2], af[ks][3], aBase + ks * 32);

    // B non-trans ldsm base: tiles = (codes 0-7 | +8) x (k-lo | k-hi)
    const u32 bBase = sb + OFF_B
        + (u32)(((lane & 7) + ((lane >> 4) & 1) * 8) * BSTRIDE + ((lane >> 3) & 1) * 16);
    const int colBase = 2 * (lane & 3);

    // packed top-2 keys per row pair
    float k1a = CUDART_INF_F, k2a = CUDART_INF_F;
    float k1b = CUDART_INF_F, k2b = CUDART_INF_F;

    // ---- mainloop: 16 subchunks of 32 codes, barrier-free ----
    #pragma unroll 1
    for (int s = 0; s < 16; ++s) {
        const int c0 = s * 32;
        const u32 bRow = bBase + (u32)(c0 * BSTRIDE);

        u32 p[4], q[4];
        ldsm_x4(p[0], p[1], p[2], p[3], bRow);                      // codes c0..c0+15
        ldsm_x4(q[0], q[1], q[2], q[3], bRow + 16 * BSTRIDE);       // codes c0+16..+31

        float2 e0 = *reinterpret_cast<const float2*>(&enorm_s[c0 +  0 + colBase]);
        float2 e1 = *reinterpret_cast<const float2*>(&enorm_s[c0 +  8 + colBase]);
        float2 e2 = *reinterpret_cast<const float2*>(&enorm_s[c0 + 16 + colBase]);
        float2 e3 = *reinterpret_cast<const float2*>(&enorm_s[c0 + 24 + colBase]);

        float acc[4][4];
        mma_f16_init(acc[0], af[0], p[0], p[1], e0.x, e0.y);
        mma_f16_init(acc[1], af[0], p[2], p[3], e1.x, e1.y);
        mma_f16_init(acc[2], af[0], q[0], q[1], e2.x, e2.y);
        mma_f16_init(acc[3], af[0], q[2], q[3], e3.x, e3.y);

        #pragma unroll
        for (int ks = 1; ks < 4; ++ks) {
            ldsm_x4(p[0], p[1], p[2], p[3], bRow + ks * 32);
            ldsm_x4(q[0], q[1], q[2], q[3], bRow + 16 * BSTRIDE + ks * 32);
            mma_f16(acc[0], af[ks], p[0], p[1]);
            mma_f16(acc[1], af[ks], p[2], p[3]);
            mma_f16(acc[2], af[ks], q[0], q[1]);
            mma_f16(acc[3], af[ks], q[2], q[3]);
        }

        #pragma unroll
        for (int nt = 0; nt < 4; ++nt) {
            int code0 = c0 + nt * 8 + colBase;
            float pk;
            #define UPD(K1, K2, VAL, IDX)                            \
                do { pk = packkey((VAL), (IDX));                     \
                     K2 = fminf(K2, fmaxf(K1, pk));                  \
                     K1 = fminf(K1, pk); } while (0)
            UPD(k1a, k2a, acc[nt][0], code0);
            UPD(k1a, k2a, acc[nt][1], code0 + 1);
            UPD(k1b, k2b, acc[nt][2], code0);
            UPD(k1b, k2b, acc[nt][3], code0 + 1);
            #undef UPD
        }
    }

    // A region dead: init flag overlay safely
    __syncthreads();
    if (tid == 0) *flagcnt = 0;
    __syncthreads();

    // ---- quad top-2 merge on COPIES (per-lane k1/k2 preserved as candidates) ----
    float m1a = k1a, m2a = k2a, m1b = k1b, m2b = k2b;
    #define MERGE(K1, K2, OFFX)                                              \
        do {                                                                 \
            float o1 = __shfl_xor_sync(0xffffffffu, K1, OFFX);               \
            float o2 = __shfl_xor_sync(0xffffffffu, K2, OFFX);               \
            K2 = fminf(fminf(K2, o2), fmaxf(K1, o1));                        \
            K1 = fminf(K1, o1);                                              \
        } while (0)
    MERGE(m1a, m2a, 1);
    MERGE(m1a, m2a, 2);
    MERGE(m1b, m2b, 1);
    MERGE(m1b, m2b, 2);
    #undef MERGE

    // flag: near-tie; crowd: some lane hides a 3rd in-band candidate -> full rescan
    bool flagA = (m2a - m1a < BAND_T);
    bool flagB = (m2b - m1b < BAND_T);
    u32 balA = __ballot_sync(0xffffffffu, k2a < m1a + BAND_T);
    u32 balB = __ballot_sync(0xffffffffu, k2b < m1b + BAND_T);
    bool crowdA = (balA >> (lane & 28)) & 0xFu;
    bool crowdB = (balB >> (lane & 28)) & 0xFu;
    bool fullA = flagA && crowdA;
    bool fullB = flagB && crowdB;
    bool refA  = flagA && !crowdA;
    bool refB  = flagB && !crowdB;

    const int rA = warpRow + (lane >> 2);
    const int rB = rA + 8;

    if ((lane & 3) == 0) {
        int i1a = (int)(__float_as_uint(m1a) & 511u);
        int i1b = (int)(__float_as_uint(m1b) & 511u);
        rowcode[rA] = i1a;
        rowcode[rB] = i1b;
        size_t pA = IDX_OFF + (size_t)(rowBase + rA);
        size_t pB = IDX_OFF + (size_t)(rowBase + rB);
        if (pA < (size_t)out_size) out[pA] = (float)i1a;
        if (pB < (size_t)out_size) out[pB] = (float)i1b;
        if (fullA) flaglist[atomicAdd(flagcnt, 1)] = rA;
        if (fullB) flaglist[atomicAdd(flagcnt, 1)] = rB;
    }

    // ---- 8-candidate exact refine for near-tie rows (no crowding) ----
    if (__any_sync(0xffffffffu, refA || refB)) {
        // row A
        {
            int c1 = (int)(__float_as_uint(k1a) & 511u);
            int c2 = (int)(__float_as_uint(k2a) & 511u);
            float d1, d2;
            exact2(X, enorm_s, rowBase + rA, c1, c2, d1, d2);
            float bv = d1; int bi = c1;
            if (d2 < bv || (d2 == bv && c2 < bi)) { bv = d2; bi = c2; }
            #pragma unroll
            for (int off = 1; off <= 2; off <<= 1) {
                float ov = __shfl_xor_sync(0xffffffffu, bv, off);
                int   oi = __shfl_xor_sync(0xffffffffu, bi, off);
                if (ov < bv || (ov == bv && oi < bi)) { bv = ov; bi = oi; }
            }
            if (refA && (lane & 3) == 0) {
                rowcode[rA] = bi;
                size_t p = IDX_OFF + (size_t)(rowBase + rA);
                if (p < (size_t)out_size) out[p] = (float)bi;
            }
        }
        // row B
        {
            int c1 = (int)(__float_as_uint(k1b) & 511u);
            int c2 = (int)(__float_as_uint(k2b) & 511u);
            float d1, d2;
            exact2(X, enorm_s, rowBase + rB, c1, c2, d1, d2);
            float bv = d1; int bi = c1;
            if (d2 < bv || (d2 == bv && c2 < bi)) { bv = d2; bi = c2; }
            #pragma unroll
            for (int off = 1; off <= 2; off <<= 1) {
                float ov = __shfl_xor_sync(0xffffffffu, bv, off);
                int   oi = __shfl_xor_sync(0xffffffffu, bi, off);
                if (ov < bv || (ov == bv && oi < bi)) { bv = ov; bi = oi; }
            }
            if (refB && (lane & 3) == 0) {
                rowcode[rB] = bi;
                size_t p = IDX_OFF + (size_t)(rowBase + rB);
                if (p < (size_t)out_size) out[p] = (float)bi;
            }
        }
    }
    __syncthreads();

    // ---- rare full fp32 rescan (crowded near-ties), one warp per row ----
    {
        int nflag = *flagcnt;
        for (int f = warp; f < nflag; f += 16) {
            int r = flaglist[f];
            const float* xr = X + (size_t)(rowBase + r) * DIM;
            float4 acc4[4];
            #pragma unroll
            for (int j = 0; j < 4; ++j) acc4[j] = make_float4(0.f, 0.f, 0.f, 0.f);
            for (int d = 0; d < DIM; ++d) {
                float xd = xr[d];
                #pragma unroll
                for (int j = 0; j < 4; ++j) {
                    float4 ev = *reinterpret_cast<const float4*>(
                        E + (size_t)d * KCODES + j * 128 + lane * 4);
                    acc4[j].x = fmaf(xd, ev.x, acc4[j].x);
                    acc4[j].y = fmaf(xd, ev.y, acc4[j].y);
                    acc4[j].z = fmaf(xd, ev.z, acc4[j].z);
                    acc4[j].w = fmaf(xd, ev.w, acc4[j].w);
                }
            }
            float bv = CUDART_INF_F;
            int   bi = 0;
            #pragma unroll
            for (int j = 0; j < 4; ++j) {
                float dv[4] = {acc4[j].x, acc4[j].y, acc4[j].z, acc4[j].w};
                #pragma unroll
                for (int e = 0; e < 4; ++e) {
                    int   c = j * 128 + lane * 4 + e;
                    float v = fmaf(-2.f, dv[e], enorm_s[c]);
                    if (v < bv) { bv = v; bi = c; }
                }
            }
            #pragma unroll
            for (int st = 16; st > 0; st >>= 1) {
                float ov = __shfl_xor_sync(0xffffffffu, bv, st);
                int   oi = __shfl_xor_sync(0xffffffffu, bi, st);
                if (ov < bv || (ov == bv && oi < bi)) { bv = ov; bi = oi; }
            }
            if (lane == 0) {
                rowcode[r] = bi;
                size_t p = IDX_OFF + (size_t)(rowBase + r);
                if (p < (size_t)out_size) out[p] = (float)bi;
            }
        }
    }
    __syncthreads();

    // ---- gather quantized via transposed ET (coalesced), loss ----
    float lsum = 0.f;
    #pragma unroll 4
    for (int i = tid; i < ROWS_BLK * DIM; i += THREADS) {
        int r = i >> 6, d = i & 63;
        int code = rowcode[r];
        float qv = g_ET[code * DIM + d];
        float xv = X[(size_t)(rowBase + r) * DIM + d];
        out[(size_t)(rowBase + r) * DIM + d] = qv;
        float df = qv - xv;
        lsum = fmaf(df, df, lsum);
    }

    // ---- block loss reduction ----
    __syncthreads();
    float* red = reinterpret_cast<float*>(smem + OFF_RED);
    red[tid] = lsum;
    __syncthreads();
    #pragma unroll
    for (int s = THREADS / 2; s > 0; s >>= 1) {
        if (tid < s) red[tid] += red[tid + s];
        __syncthreads();
    }

    // ---- last-block deterministic final loss reduction ----
    __shared__ int islast;
    if (tid == 0) {
        g_partials[blockIdx.x] = red[0];
        __threadfence();
        int tk = atomicAdd(&g_done, 1);
        islast = (tk == NCTAS - 1) ? 1 : 0;
    }
    __syncthreads();
    if (islast) {
        volatile float* gp = g_partials;
        float s = (tid < NCTAS) ? gp[tid] : 0.f;
        red[tid] = s;
        __syncthreads();
        #pragma unroll
        for (int st = THREADS / 2; st > 0; st >>= 1) {
            if (tid < st) red[tid] += red[tid + st];
            __syncthreads();
        }
        if (tid == 0) {
            float loss = 1.25f * red[0] / (float)Q_ELEMS;
            if (LOSS_OFF < (size_t)out_size) out[LOSS_OFF] = loss;
            g_done = 0;                     // reset for next graph replay
        }
    }
}

// ---------------------------------------------------------------------------
extern "C" void kernel_launch(void* const* d_in, const int* in_sizes, int n_in,
                              void* d_out, int out_size) {
    const float* X;
    const float* E;
    if (in_sizes[0] == DIM * KCODES && in_sizes[1] != DIM * KCODES) {
        E = (const float*)d_in[0];
        X = (const float*)d_in[1];
    } else {
        X = (const float*)d_in[0];
        E = (const float*)d_in[1];
    }
    float* out = (float*)d_out;

    static bool attr_done = false;
    if (!attr_done) {
        cudaFuncSetAttribute(vq_kernel,
                             cudaFuncAttributeMaxDynamicSharedMemorySize, SMEM_TOTAL);
        attr_done = true;
    }

    vq_prep_kernel<<<64, 512>>>(E);
    vq_kernel<<<NCTAS, THREADS, SMEM_TOTAL>>>(X, E, out, out_size);
}

// round 14
// speedup vs baseline: 1.7199x; 1.7199x over previous
#include <cuda_runtime.h>
#include <cuda_fp16.h>
#include <math_constants.h>

typedef unsigned int u32;

// Problem: inputs [64,32,32,64] f32 -> N=65536 rows, D=64; embeddings [64,512] f32.
// Output (f32 concat): quantized [N*64] | indices [N] | loss [1]
#define N_ROWS   65536
#define DIM      64
#define KCODES   512
#define ROWS_BLK 256
#define THREADS  512
#define NCTAS    (N_ROWS / ROWS_BLK)     // 256 CTAs, single wave

#define Q_ELEMS  ((size_t)N_ROWS * DIM)
#define IDX_OFF  Q_ELEMS
#define LOSS_OFF (Q_ELEMS + N_ROWS)

// SMEM layout (bytes)
#define ASTRIDE   144                    // A: 128B fp16 row + 16B pad
#define BSTRIDE   144                    // B: [code][d] 128B row + 16B pad
#define OFF_A     0                                   // 256*144 = 36864
#define OFF_B     (OFF_A + ROWS_BLK * ASTRIDE)        // 36864
#define OFF_ENORM (OFF_B + KCODES * BSTRIDE)          // 110592
#define SMEM_TOTAL (OFF_ENORM + KCODES * 4)           // 112640 -> 2 CTAs/SM
// post-mainloop overlays inside dead A region (36 KB available):
#define OFF_FLAGC   0
#define OFF_REFC    16
#define OFF_FLAGL   32                                // up to 256 ints
#define OFF_REFL    1056                              // up to 256 ints
#define OFF_ROWCODE 2080                              // 256 ints
#define OFF_CAND    3136                              // 256 x 8 ints = 8192 B
#define OFF_RED     11392                             // 512 floats

// fp16 flip band ~0.075 worst-case + packing 0.001 -> 0.09 is rigorous.
#define BAND_T 0.09f

__device__ float  g_partials[NCTAS];
__device__ int    g_done = 0;
__device__ __half g_B2h[KCODES * DIM];   // fp16 (-2*E), [code][d]
__device__ float  g_ET[KCODES * DIM];    // fp32 E transposed, [code][d]
__device__ float  g_enorm[KCODES];

// ---------------------------------------------------------------------------
static __device__ __forceinline__ u32 smem_u32(const void* p) {
    u32 a;
    asm("{ .reg .u64 t; cvta.to.shared.u64 t, %1; cvt.u32.u64 %0, t; }" : "=r"(a) : "l"(p));
    return a;
}
static __device__ __forceinline__ void ldsm_x4(u32& r0, u32& r1, u32& r2, u32& r3, u32 a) {
    asm volatile("ldmatrix.sync.aligned.m8n8.x4.shared.b16 {%0,%1,%2,%3}, [%4];"
                 : "=r"(r0), "=r"(r1), "=r"(r2), "=r"(r3) : "r"(a));
}
static __device__ __forceinline__ void mma_f16(float* c, const u32* a, u32 b0, u32 b1) {
    asm volatile("mma.sync.aligned.m16n8k16.row.col.f32.f16.f16.f32 "
                 "{%0,%1,%2,%3}, {%4,%5,%6,%7}, {%8,%9}, {%0,%1,%2,%3};"
                 : "+f"(c[0]), "+f"(c[1]), "+f"(c[2]), "+f"(c[3])
                 : "r"(a[0]), "r"(a[1]), "r"(a[2]), "r"(a[3]), "r"(b0), "r"(b1));
}
static __device__ __forceinline__ void mma_f16_init(float* d, const u32* a, u32 b0, u32 b1,
                                                    float e0, float e1) {
    asm volatile("mma.sync.aligned.m16n8k16.row.col.f32.f16.f16.f32 "
                 "{%0,%1,%2,%3}, {%4,%5,%6,%7}, {%8,%9}, {%10,%11,%10,%11};"
                 : "=f"(d[0]), "=f"(d[1]), "=f"(d[2]), "=f"(d[3])
                 : "r"(a[0]), "r"(a[1]), "r"(a[2]), "r"(a[3]), "r"(b0), "r"(b1),
                   "f"(e0), "f"(e1));
}
// pack code into low 9 mantissa bits (|dist_rel|<16 -> pack error < 1e-3)
static __device__ __forceinline__ float packkey(float v, int code) {
    return __uint_as_float((__float_as_uint(v) & 0xFFFFFE00u) | (u32)code);
}

// ---------------------------------------------------------------------------
// Kernel 1: prep — fp16 (-2E) [code][d], fp32 E^T, enorm
// ---------------------------------------------------------------------------
__global__ void vq_prep_kernel(const float* __restrict__ E) {
    int gid = blockIdx.x * 512 + threadIdx.x;        // 0..32767 == d*512 + code
    float v = E[gid];
    int d = gid >> 9, c = gid & 511;
    g_B2h[c * DIM + d] = __float2half_rn(-2.f * v);
    g_ET[c * DIM + d]  = v;
    if (gid < KCODES) {
        float s = 0.f;
        #pragma unroll 16
        for (int dd = 0; dd < DIM; ++dd) {
            float e = E[(size_t)dd * KCODES + gid];
            s = fmaf(e, e, s);
        }
        g_enorm[gid] = s;
    }
}

// ---------------------------------------------------------------------------
// Kernel 2: main — fp16 GEMM mainloop + warp-cooperative candidate refine
// ---------------------------------------------------------------------------
__global__ void __launch_bounds__(THREADS, 2)
vq_kernel(const float* __restrict__ X, const float* __restrict__ E,
          float* __restrict__ out, int out_size) {
    extern __shared__ char smem[];
    const u32 sb   = smem_u32(smem);
    const int tid  = threadIdx.x;
    const int lane = tid & 31;
    const int warp = tid >> 5;                // 0..15
    const int rowBase = blockIdx.x * ROWS_BLK;
    const int warpRow = warp * 16;

    float* enorm_s  = reinterpret_cast<float*>(smem + OFF_ENORM);
    int*   rowcode  = reinterpret_cast<int*>(smem + OFF_ROWCODE);
    int*   flagcnt  = reinterpret_cast<int*>(smem + OFF_FLAGC);
    int*   refcnt   = reinterpret_cast<int*>(smem + OFF_REFC);
    int*   flaglist = reinterpret_cast<int*>(smem + OFF_FLAGL);
    int*   reflist  = reinterpret_cast<int*>(smem + OFF_REFL);
    int*   cand     = reinterpret_cast<int*>(smem + OFF_CAND);

    // ---- A tile: fp32 -> fp16, [row][d] stride 144 ----
    #pragma unroll
    for (int it = 0; it < 4; ++it) {
        int task = tid + THREADS * it;        // 2048 tasks: 256 rows x 8 groups
        int r  = task >> 3;
        int d0 = (task & 7) * 8;
        const float4* xv = reinterpret_cast<const float4*>(
            X + (size_t)(rowBase + r) * DIM + d0);
        float4 v0 = xv[0], v1 = xv[1];
        float vals[8] = {v0.x, v0.y, v0.z, v0.w, v1.x, v1.y, v1.z, v1.w};
        union { __half h[8]; uint4 u; } ph;
        #pragma unroll
        for (int e = 0; e < 8; ++e) ph.h[e] = __float2half_rn(vals[e]);
        *reinterpret_cast<uint4*>(smem + OFF_A + r * ASTRIDE + d0 * 2) = ph.u;
    }
    // ---- B: copy -2E fp16 [code][d] rows (stride 144) ----
    {
        const uint4* src = reinterpret_cast<const uint4*>(g_B2h);
        #pragma unroll
        for (int it = 0; it < 8; ++it) {
            int i = tid + THREADS * it;       // 4096 uint4: 512 codes x 8 groups
            int c = i >> 3, q = i & 7;
            *reinterpret_cast<uint4*>(smem + OFF_B + c * BSTRIDE + q * 16) = src[i];
        }
    }
    enorm_s[tid] = g_enorm[tid];
    __syncthreads();

    // ---- hoisted A fragments ----
    const int mA = lane >> 3, rA8 = lane & 7;
    const u32 aBase = sb + OFF_A + (u32)((warpRow + (mA & 1) * 8 + rA8) * ASTRIDE
                                         + (mA >> 1) * 16);
    u32 af[4][4];
    #pragma unroll
    for (int ks = 0; ks < 4; ++ks)
        ldsm_x4(af[ks][0], af[ks][1], af[ks][2], af[ks][3], aBase + ks * 32);

    // B non-trans ldsm base: tiles = (codes 0-7 | +8) x (k-lo | k-hi)
    const u32 bBase = sb + OFF_B
        + (u32)(((lane & 7) + ((lane >> 4) & 1) * 8) * BSTRIDE + ((lane >> 3) & 1) * 16);
    const int colBase = 2 * (lane & 3);

    // packed top-2 keys per row pair
    float k1a = CUDART_INF_F, k2a = CUDART_INF_F;
    float k1b = CUDART_INF_F, k2b = CUDART_INF_F;

    // ---- mainloop: 16 subchunks of 32 codes, barrier-free ----
    #pragma unroll 1
    for (int s = 0; s < 16; ++s) {
        const int c0 = s * 32;
        const u32 bRow = bBase + (u32)(c0 * BSTRIDE);

        u32 p[4], q[4];
        ldsm_x4(p[0], p[1], p[2], p[3], bRow);                      // codes c0..c0+15
        ldsm_x4(q[0], q[1], q[2], q[3], bRow + 16 * BSTRIDE);       // codes c0+16..+31

        float2 e0 = *reinterpret_cast<const float2*>(&enorm_s[c0 +  0 + colBase]);
        float2 e1 = *reinterpret_cast<const float2*>(&enorm_s[c0 +  8 + colBase]);
        float2 e2 = *reinterpret_cast<const float2*>(&enorm_s[c0 + 16 + colBase]);
        float2 e3 = *reinterpret_cast<const float2*>(&enorm_s[c0 + 24 + colBase]);

        float acc[4][4];
        mma_f16_init(acc[0], af[0], p[0], p[1], e0.x, e0.y);
        mma_f16_init(acc[1], af[0], p[2], p[3], e1.x, e1.y);
        mma_f16_init(acc[2], af[0], q[0], q[1], e2.x, e2.y);
        mma_f16_init(acc[3], af[0], q[2], q[3], e3.x, e3.y);

        #pragma unroll
        for (int ks = 1; ks < 4; ++ks) {
            ldsm_x4(p[0], p[1], p[2], p[3], bRow + ks * 32);
            ldsm_x4(q[0], q[1], q[2], q[3], bRow + 16 * BSTRIDE + ks * 32);
            mma_f16(acc[0], af[ks], p[0], p[1]);
            mma_f16(acc[1], af[ks], p[2], p[3]);
            mma_f16(acc[2], af[ks], q[0], q[1]);
            mma_f16(acc[3], af[ks], q[2], q[3]);
        }

        #pragma unroll
        for (int nt = 0; nt < 4; ++nt) {
            int code0 = c0 + nt * 8 + colBase;
            float pk;
            #define UPD(K1, K2, VAL, IDX)                            \
                do { pk = packkey((VAL), (IDX));                     \
                     K2 = fminf(K2, fmaxf(K1, pk));                  \
                     K1 = fminf(K1, pk); } while (0)
            UPD(k1a, k2a, acc[nt][0], code0);
            UPD(k1a, k2a, acc[nt][1], code0 + 1);
            UPD(k1b, k2b, acc[nt][2], code0);
            UPD(k1b, k2b, acc[nt][3], code0 + 1);
            #undef UPD
        }
    }

    // A region dead: init overlay counters safely
    __syncthreads();
    if (tid == 0) { *flagcnt = 0; *refcnt = 0; }
    __syncthreads();

    // ---- quad top-2 merge on COPIES (per-lane k1/k2 preserved as candidates) ----
    float m1a = k1a, m2a = k2a, m1b = k1b, m2b = k2b;
    #define MERGE(K1, K2, OFFX)                                              \
        do {                                                                 \
            float o1 = __shfl_xor_sync(0xffffffffu, K1, OFFX);               \
            float o2 = __shfl_xor_sync(0xffffffffu, K2, OFFX);               \
            K2 = fminf(fminf(K2, o2), fmaxf(K1, o1));                        \
            K1 = fminf(K1, o1);                                              \
        } while (0)
    MERGE(m1a, m2a, 1);
    MERGE(m1a, m2a, 2);
    MERGE(m1b, m2b, 1);
    MERGE(m1b, m2b, 2);
    #undef MERGE

    const int rA = warpRow + (lane >> 2);
    const int rB = rA + 8;

    // store candidate codes (quad's 8 per row)
    cand[rA * 8 + (lane & 3) * 2 + 0] = (int)(__float_as_uint(k1a) & 511u);
    cand[rA * 8 + (lane & 3) * 2 + 1] = (int)(__float_as_uint(k2a) & 511u);
    cand[rB * 8 + (lane & 3) * 2 + 0] = (int)(__float_as_uint(k1b) & 511u);
    cand[rB * 8 + (lane & 3) * 2 + 1] = (int)(__float_as_uint(k2b) & 511u);

    // flag: near-tie; crowd: some lane may hide a 3rd in-band code -> full rescan
    bool flagA = (m2a - m1a < BAND_T);
    bool flagB = (m2b - m1b < BAND_T);
    u32 balA = __ballot_sync(0xffffffffu, k2a < m1a + BAND_T);
    u32 balB = __ballot_sync(0xffffffffu, k2b < m1b + BAND_T);
    bool crowdA = (balA >> (lane & 28)) & 0xFu;
    bool crowdB = (balB >> (lane & 28)) & 0xFu;

    if ((lane & 3) == 0) {
        int i1a = (int)(__float_as_uint(m1a) & 511u);
        int i1b = (int)(__float_as_uint(m1b) & 511u);
        rowcode[rA] = i1a;
        rowcode[rB] = i1b;
        size_t pA = IDX_OFF + (size_t)(rowBase + rA);
        size_t pB = IDX_OFF + (size_t)(rowBase + rB);
        if (pA < (size_t)out_size) out[pA] = (float)i1a;
        if (pB < (size_t)out_size) out[pB] = (float)i1b;
        if (flagA) {
            if (crowdA) flaglist[atomicAdd(flagcnt, 1)] = rA;
            else        reflist[atomicAdd(refcnt, 1)]   = rA;
        }
        if (flagB) {
            if (crowdB) flaglist[atomicAdd(flagcnt, 1)] = rB;
            else        reflist[atomicAdd(refcnt, 1)]   = rB;
        }
    }
    __syncthreads();

    // ---- warp-cooperative 8-candidate exact refine (one warp per row) ----
    {
        int nref = *refcnt;
        for (int f = warp; f < nref; f += 16) {
            int r = reflist[f];
            int c = cand[r * 8 + (lane >> 2)];           // candidate for this lane group
            int seg = (lane & 3) * 16;                   // 16 dims per lane
            const float4* x4 = reinterpret_cast<const float4*>(
                X + (size_t)(rowBase + r) * DIM + seg);
            const float4* e4 = reinterpret_cast<const float4*>(g_ET + c * DIM + seg);
            float s = 0.f;
            #pragma unroll
            for (int i = 0; i < 4; ++i) {
                float4 xv = x4[i];
                float4 ev = e4[i];
                s = fmaf(xv.x, ev.x, s);
                s = fmaf(xv.y, ev.y, s);
                s = fmaf(xv.z, ev.z, s);
                s = fmaf(xv.w, ev.w, s);
            }
            // sum within the 4-lane group
            s += __shfl_xor_sync(0xffffffffu, s, 1);
            s += __shfl_xor_sync(0xffffffffu, s, 2);
            float dist = fmaf(-2.f, s, enorm_s[c]);
            // min across 8 candidate groups (index tie-break)
            float bv = dist; int bi = c;
            #pragma unroll
            for (int off = 4; off <= 16; off <<= 1) {
                float ov = __shfl_xor_sync(0xffffffffu, bv, off);
                int   oi = __shfl_xor_sync(0xffffffffu, bi, off);
                if (ov < bv || (ov == bv && oi < bi)) { bv = ov; bi = oi; }
            }
            if (lane == 0) {
                rowcode[r] = bi;
                size_t p = IDX_OFF + (size_t)(rowBase + r);
                if (p < (size_t)out_size) out[p] = (float)bi;
            }
        }
    }

    // ---- rare full fp32 rescan (crowded near-ties), one warp per row ----
    {
        int nflag = *flagcnt;
        for (int f = warp; f < nflag; f += 16) {
            int r = flaglist[f];
            const float* xr = X + (size_t)(rowBase + r) * DIM;
            float4 acc4[4];
            #pragma unroll
            for (int j = 0; j < 4; ++j) acc4[j] = make_float4(0.f, 0.f, 0.f, 0.f);
            for (int d = 0; d < DIM; ++d) {
                float xd = xr[d];
                #pragma unroll
                for (int j = 0; j < 4; ++j) {
                    float4 ev = *reinterpret_cast<const float4*>(
                        E + (size_t)d * KCODES + j * 128 + lane * 4);
                    acc4[j].x = fmaf(xd, ev.x, acc4[j].x);
                    acc4[j].y = fmaf(xd, ev.y, acc4[j].y);
                    acc4[j].z = fmaf(xd, ev.z, acc4[j].z);
                    acc4[j].w = fmaf(xd, ev.w, acc4[j].w);
                }
            }
            float bv = CUDART_INF_F;
            int   bi = 0;
            #pragma unroll
            for (int j = 0; j < 4; ++j) {
                float dv[4] = {acc4[j].x, acc4[j].y, acc4[j].z, acc4[j].w};
                #pragma unroll
                for (int e = 0; e < 4; ++e) {
                    int   c = j * 128 + lane * 4 + e;
                    float v = fmaf(-2.f, dv[e], enorm_s[c]);
                    if (v < bv) { bv = v; bi = c; }
                }
            }
            #pragma unroll
            for (int st = 16; st > 0; st >>= 1) {
                float ov = __shfl_xor_sync(0xffffffffu, bv, st);
                int   oi = __shfl_xor_sync(0xffffffffu, bi, st);
                if (ov < bv || (ov == bv && oi < bi)) { bv = ov; bi = oi; }
            }
            if (lane == 0) {
                rowcode[r] = bi;
                size_t p = IDX_OFF + (size_t)(rowBase + r);
                if (p < (size_t)out_size) out[p] = (float)bi;
            }
        }
    }
    __syncthreads();

    // ---- gather quantized via transposed ET (coalesced), loss ----
    float lsum = 0.f;
    #pragma unroll 4
    for (int i = tid; i < ROWS_BLK * DIM; i += THREADS) {
        int r = i >> 6, d = i & 63;
        int code = rowcode[r];
        float qv = g_ET[code * DIM + d];
        float xv = X[(size_t)(rowBase + r) * DIM + d];
        out[(size_t)(rowBase + r) * DIM + d] = qv;
        float df = qv - xv;
        lsum = fmaf(df, df, lsum);
    }

    // ---- block loss reduction ----
    __syncthreads();
    float* red = reinterpret_cast<float*>(smem + OFF_RED);
    red[tid] = lsum;
    __syncthreads();
    #pragma unroll
    for (int s = THREADS / 2; s > 0; s >>= 1) {
        if (tid < s) red[tid] += red[tid + s];
        __syncthreads();
    }

    // ---- last-block deterministic final loss reduction ----
    __shared__ int islast;
    if (tid == 0) {
        g_partials[blockIdx.x] = red[0];
        __threadfence();
        int tk = atomicAdd(&g_done, 1);
        islast = (tk == NCTAS - 1) ? 1 : 0;
    }
    __syncthreads();
    if (islast) {
        volatile float* gp = g_partials;
        float s = (tid < NCTAS) ? gp[tid] : 0.f;
        red[tid] = s;
        __syncthreads();
        #pragma unroll
        for (int st = THREADS / 2; st > 0; st >>= 1) {
            if (tid < st) red[tid] += red[tid + st];
            __syncthreads();
        }
        if (tid == 0) {
            float loss = 1.25f * red[0] / (float)Q_ELEMS;
            if (LOSS_OFF < (size_t)out_size) out[LOSS_OFF] = loss;
            g_done = 0;                     // reset for next graph replay
        }
    }
}

// ---------------------------------------------------------------------------
extern "C" void kernel_launch(void* const* d_in, const int* in_sizes, int n_in,
                              void* d_out, int out_size) {
    const float* X;
    const float* E;
    if (in_sizes[0] == DIM * KCODES && in_sizes[1] != DIM * KCODES) {
        E = (const float*)d_in[0];
        X = (const float*)d_in[1];
    } else {
        X = (const float*)d_in[0];
        E = (const float*)d_in[1];
    }
    float* out = (float*)d_out;

    static bool attr_done = false;
    if (!attr_done) {
        cudaFuncSetAttribute(vq_kernel,
                             cudaFuncAttributeMaxDynamicSharedMemorySize, SMEM_TOTAL);
        attr_done = true;
    }

    vq_prep_kernel<<<64, 512>>>(E);
    vq_kernel<<<NCTAS, THREADS, SMEM_TOTAL>>>(X, E, out, out_size);
}

// round 15
// speedup vs baseline: 1.7795x; 1.0347x over previous
#include <cuda_runtime.h>
#include <cuda_fp16.h>
#include <math_constants.h>

typedef unsigned int u32;

// Problem: inputs [64,32,32,64] f32 -> N=65536 rows, D=64; embeddings [64,512] f32.
// Output (f32 concat): quantized [N*64] | indices [N] | loss [1]
#define N_ROWS   65536
#define DIM      64
#define KCODES   512
#define ROWS_BLK 256
#define THREADS  512
#define NCTAS    (N_ROWS / ROWS_BLK)     // 256 CTAs, single wave

#define Q_ELEMS  ((size_t)N_ROWS * DIM)
#define IDX_OFF  Q_ELEMS
#define LOSS_OFF (Q_ELEMS + N_ROWS)

// SMEM layout (bytes)
#define ASTRIDE   144                    // A: 128B fp16 row + 16B pad
#define BSTRIDE   144                    // B: [code][d] 128B row + 16B pad
#define OFF_A     0                                   // 256*144 = 36864
#define OFF_B     (OFF_A + ROWS_BLK * ASTRIDE)        // 36864
#define OFF_ENORM (OFF_B + KCODES * BSTRIDE)          // 110592
#define SMEM_TOTAL (OFF_ENORM + KCODES * 4)           // 112640 -> 2 CTAs/SM
// post-mainloop overlays inside dead A region (36 KB available):
#define OFF_FLAGC   0
#define OFF_REFC    16
#define OFF_FLAGL   32                                // up to 256 ints
#define OFF_REFL    1056                              // up to 256 ints
#define OFF_ROWCODE 2080                              // 256 ints
#define OFF_CAND    3136                              // 256 x 8 ints = 8192 B
#define OFF_RED     11392                             // 512 floats

// fp16 flip band ~0.075 worst-case + packing 0.001 -> 0.09 is rigorous.
#define BAND_T 0.09f

__device__ float  g_partials[NCTAS];
__device__ int    g_done = 0;
__device__ __half g_B2h[KCODES * DIM];   // fp16 (-2*E), [code][d]
__device__ float  g_ET[KCODES * DIM];    // fp32 E transposed, [code][d]
__device__ float  g_enorm[KCODES];

// ---------------------------------------------------------------------------
static __device__ __forceinline__ u32 smem_u32(const void* p) {
    u32 a;
    asm("{ .reg .u64 t; cvta.to.shared.u64 t, %1; cvt.u32.u64 %0, t; }" : "=r"(a) : "l"(p));
    return a;
}
static __device__ __forceinline__ void ldsm_x4(u32& r0, u32& r1, u32& r2, u32& r3, u32 a) {
    asm volatile("ldmatrix.sync.aligned.m8n8.x4.shared.b16 {%0,%1,%2,%3}, [%4];"
                 : "=r"(r0), "=r"(r1), "=r"(r2), "=r"(r3) : "r"(a));
}
static __device__ __forceinline__ void mma_f16(float* c, const u32* a, u32 b0, u32 b1) {
    asm volatile("mma.sync.aligned.m16n8k16.row.col.f32.f16.f16.f32 "
                 "{%0,%1,%2,%3}, {%4,%5,%6,%7}, {%8,%9}, {%0,%1,%2,%3};"
                 : "+f"(c[0]), "+f"(c[1]), "+f"(c[2]), "+f"(c[3])
                 : "r"(a[0]), "r"(a[1]), "r"(a[2]), "r"(a[3]), "r"(b0), "r"(b1));
}
static __device__ __forceinline__ void mma_f16_init(float* d, const u32* a, u32 b0, u32 b1,
                                                    float e0, float e1) {
    asm volatile("mma.sync.aligned.m16n8k16.row.col.f32.f16.f16.f32 "
                 "{%0,%1,%2,%3}, {%4,%5,%6,%7}, {%8,%9}, {%10,%11,%10,%11};"
                 : "=f"(d[0]), "=f"(d[1]), "=f"(d[2]), "=f"(d[3])
                 : "r"(a[0]), "r"(a[1]), "r"(a[2]), "r"(a[3]), "r"(b0), "r"(b1),
                   "f"(e0), "f"(e1));
}
// pack code into low 9 mantissa bits (|dist_rel|<16 -> pack error < 1e-3)
static __device__ __forceinline__ float packkey(float v, int code) {
    return __uint_as_float((__float_as_uint(v) & 0xFFFFFE00u) | (u32)code);
}
#define CP_ASYNC16(dst, src) \
    asm volatile("cp.async.cg.shared.global [%0], [%1], 16;" :: "r"(dst), "l"(src))
#define CP_COMMIT() asm volatile("cp.async.commit_group;" ::: "memory")
#define CP_WAIT0()  asm volatile("cp.async.wait_group 0;" ::: "memory")

// ---------------------------------------------------------------------------
// Kernel 1: prep — fp16 (-2E) [code][d], fp32 E^T, enorm
// ---------------------------------------------------------------------------
__global__ void vq_prep_kernel(const float* __restrict__ E) {
    int gid = blockIdx.x * 512 + threadIdx.x;        // 0..32767 == d*512 + code
    float v = E[gid];
    int d = gid >> 9, c = gid & 511;
    g_B2h[c * DIM + d] = __float2half_rn(-2.f * v);
    g_ET[c * DIM + d]  = v;
    if (gid < KCODES) {
        float s = 0.f;
        #pragma unroll 16
        for (int dd = 0; dd < DIM; ++dd) {
            float e = E[(size_t)dd * KCODES + gid];
            s = fmaf(e, e, s);
        }
        g_enorm[gid] = s;
    }
}

// ---------------------------------------------------------------------------
// Kernel 2: main — pipelined fp16 GEMM mainloop + candidate refine
// ---------------------------------------------------------------------------
__global__ void __launch_bounds__(THREADS, 2)
vq_kernel(const float* __restrict__ X, const float* __restrict__ E,
          float* __restrict__ out, int out_size) {
    extern __shared__ char smem[];
    const u32 sb   = smem_u32(smem);
    const int tid  = threadIdx.x;
    const int lane = tid & 31;
    const int warp = tid >> 5;                // 0..15
    const int rowBase = blockIdx.x * ROWS_BLK;
    const int warpRow = warp * 16;

    float* enorm_s  = reinterpret_cast<float*>(smem + OFF_ENORM);
    int*   rowcode  = reinterpret_cast<int*>(smem + OFF_ROWCODE);
    int*   flagcnt  = reinterpret_cast<int*>(smem + OFF_FLAGC);
    int*   refcnt   = reinterpret_cast<int*>(smem + OFF_REFC);
    int*   flaglist = reinterpret_cast<int*>(smem + OFF_FLAGL);
    int*   reflist  = reinterpret_cast<int*>(smem + OFF_REFL);
    int*   cand     = reinterpret_cast<int*>(smem + OFF_CAND);

    // ---- B: cp.async straight copy (overlaps A conversion below) ----
    {
        const char* src = reinterpret_cast<const char*>(g_B2h);
        #pragma unroll
        for (int it = 0; it < 8; ++it) {
            int i = tid + THREADS * it;       // 4096 uint4: 512 codes x 8 groups
            int c = i >> 3, q = i & 7;
            CP_ASYNC16(sb + OFF_B + c * BSTRIDE + q * 16, src + i * 16);
        }
        CP_COMMIT();
    }

    // ---- A tile: fp32 -> fp16, [row][d] stride 144 ----
    #pragma unroll
    for (int it = 0; it < 4; ++it) {
        int task = tid + THREADS * it;        // 2048 tasks: 256 rows x 8 groups
        int r  = task >> 3;
        int d0 = (task & 7) * 8;
        const float4* xv = reinterpret_cast<const float4*>(
            X + (size_t)(rowBase + r) * DIM + d0);
        float4 v0 = xv[0], v1 = xv[1];
        float vals[8] = {v0.x, v0.y, v0.z, v0.w, v1.x, v1.y, v1.z, v1.w};
        union { __half h[8]; uint4 u; } ph;
        #pragma unroll
        for (int e = 0; e < 8; ++e) ph.h[e] = __float2half_rn(vals[e]);
        *reinterpret_cast<uint4*>(smem + OFF_A + r * ASTRIDE + d0 * 2) = ph.u;
    }
    enorm_s[tid] = g_enorm[tid];
    CP_WAIT0();
    __syncthreads();

    // ---- hoisted A fragments ----
    const int mA = lane >> 3, rA8 = lane & 7;
    const u32 aBase = sb + OFF_A + (u32)((warpRow + (mA & 1) * 8 + rA8) * ASTRIDE
                                         + (mA >> 1) * 16);
    u32 af[4][4];
    #pragma unroll
    for (int ks = 0; ks < 4; ++ks)
        ldsm_x4(af[ks][0], af[ks][1], af[ks][2], af[ks][3], aBase + ks * 32);

    // B non-trans ldsm base: tiles = (codes 0-7 | +8) x (k-lo | k-hi)
    const u32 bBase = sb + OFF_B
        + (u32)(((lane & 7) + ((lane >> 4) & 1) * 8) * BSTRIDE + ((lane >> 3) & 1) * 16);
    const int colBase = 2 * (lane & 3);

    // packed top-2 keys per row pair
    float k1a = CUDART_INF_F, k2a = CUDART_INF_F;
    float k1b = CUDART_INF_F, k2b = CUDART_INF_F;

    // ---- pipelined mainloop: 32 half-chunks of 16 codes, 2 acc buffers ----
    float accA[8], accB[8];

    // issue half h's 4 LDSM + 8 MMA into acc[0..7]
    #define ISSUE_HALF(H, ACC)                                                   \
        do {                                                                     \
            const u32 bRow = bBase + (u32)((H) * 16 * BSTRIDE);                  \
            float2 eL = *reinterpret_cast<const float2*>(                        \
                &enorm_s[(H) * 16 + colBase]);                                   \
            float2 eH = *reinterpret_cast<const float2*>(                        \
                &enorm_s[(H) * 16 + 8 + colBase]);                               \
            u32 p0, p1, p2, p3;                                                  \
            ldsm_x4(p0, p1, p2, p3, bRow);                                       \
            mma_f16_init((ACC) + 0, af[0], p0, p1, eL.x, eL.y);                  \
            mma_f16_init((ACC) + 4, af[0], p2, p3, eH.x, eH.y);                  \
            ldsm_x4(p0, p1, p2, p3, bRow + 32);                                  \
            mma_f16((ACC) + 0, af[1], p0, p1);                                   \
            mma_f16((ACC) + 4, af[1], p2, p3);                                   \
            ldsm_x4(p0, p1, p2, p3, bRow + 64);                                  \
            mma_f16((ACC) + 0, af[2], p0, p1);                                   \
            mma_f16((ACC) + 4, af[2], p2, p3);                                   \
            ldsm_x4(p0, p1, p2, p3, bRow + 96);                                  \
            mma_f16((ACC) + 0, af[3], p0, p1);                                   \
            mma_f16((ACC) + 4, af[3], p2, p3);                                   \
        } while (0)

    #define UPD(K1, K2, VAL, IDX)                                \
        do { float pk = packkey((VAL), (IDX));                   \
             K2 = fminf(K2, fmaxf(K1, pk));                      \
             K1 = fminf(K1, pk); } while (0)

    // consume half h's acc (distances already include enorm via C-init)
    #define UPD_HALF(H, ACC)                                                     \
        do {                                                                     \
            int code0 = (H) * 16 + colBase;                                      \
            UPD(k1a, k2a, (ACC)[0], code0);                                      \
            UPD(k1a, k2a, (ACC)[1], code0 + 1);                                  \
            UPD(k1b, k2b, (ACC)[2], code0);                                      \
            UPD(k1b, k2b, (ACC)[3], code0 + 1);                                  \
            UPD(k1a, k2a, (ACC)[4], code0 + 8);                                  \
            UPD(k1a, k2a, (ACC)[5], code0 + 9);                                  \
            UPD(k1b, k2b, (ACC)[6], code0 + 8);                                  \
            UPD(k1b, k2b, (ACC)[7], code0 + 9);                                  \
        } while (0)

    ISSUE_HALF(0, accA);
    #pragma unroll 1
    for (int h = 0; h < 15; ++h) {
        ISSUE_HALF(2 * h + 1, accB);
        UPD_HALF(2 * h, accA);
        ISSUE_HALF(2 * h + 2, accA);
        UPD_HALF(2 * h + 1, accB);
    }
    ISSUE_HALF(31, accB);
    UPD_HALF(30, accA);
    UPD_HALF(31, accB);
    #undef ISSUE_HALF
    #undef UPD_HALF
    #undef UPD

    // A region dead: init overlay counters safely
    __syncthreads();
    if (tid == 0) { *flagcnt = 0; *refcnt = 0; }
    __syncthreads();

    // ---- quad top-2 merge on COPIES (per-lane k1/k2 preserved as candidates) ----
    float m1a = k1a, m2a = k2a, m1b = k1b, m2b = k2b;
    #define MERGE(K1, K2, OFFX)                                              \
        do {                                                                 \
            float o1 = __shfl_xor_sync(0xffffffffu, K1, OFFX);               \
            float o2 = __shfl_xor_sync(0xffffffffu, K2, OFFX);               \
            K2 = fminf(fminf(K2, o2), fmaxf(K1, o1));                        \
            K1 = fminf(K1, o1);                                              \
        } while (0)
    MERGE(m1a, m2a, 1);
    MERGE(m1a, m2a, 2);
    MERGE(m1b, m2b, 1);
    MERGE(m1b, m2b, 2);
    #undef MERGE

    const int rA = warpRow + (lane >> 2);
    const int rB = rA + 8;

    // store candidate codes (quad's 8 per row)
    cand[rA * 8 + (lane & 3) * 2 + 0] = (int)(__float_as_uint(k1a) & 511u);
    cand[rA * 8 + (lane & 3) * 2 + 1] = (int)(__float_as_uint(k2a) & 511u);
    cand[rB * 8 + (lane & 3) * 2 + 0] = (int)(__float_as_uint(k1b) & 511u);
    cand[rB * 8 + (lane & 3) * 2 + 1] = (int)(__float_as_uint(k2b) & 511u);

    // flag: near-tie; crowd: some lane may hide a 3rd in-band code -> full rescan
    bool flagA = (m2a - m1a < BAND_T);
    bool flagB = (m2b - m1b < BAND_T);
    u32 balA = __ballot_sync(0xffffffffu, k2a < m1a + BAND_T);
    u32 balB = __ballot_sync(0xffffffffu, k2b < m1b + BAND_T);
    bool crowdA = (balA >> (lane & 28)) & 0xFu;
    bool crowdB = (balB >> (lane & 28)) & 0xFu;

    if ((lane & 3) == 0) {
        int i1a = (int)(__float_as_uint(m1a) & 511u);
        int i1b = (int)(__float_as_uint(m1b) & 511u);
        rowcode[rA] = i1a;
        rowcode[rB] = i1b;
        size_t pA = IDX_OFF + (size_t)(rowBase + rA);
        size_t pB = IDX_OFF + (size_t)(rowBase + rB);
        if (pA < (size_t)out_size) out[pA] = (float)i1a;
        if (pB < (size_t)out_size) out[pB] = (float)i1b;
        if (flagA) {
            if (crowdA) flaglist[atomicAdd(flagcnt, 1)] = rA;
            else        reflist[atomicAdd(refcnt, 1)]   = rA;
        }
        if (flagB) {
            if (crowdB) flaglist[atomicAdd(flagcnt, 1)] = rB;
            else        reflist[atomicAdd(refcnt, 1)]   = rB;
        }
    }
    __syncthreads();

    // ---- warp-cooperative 8-candidate exact refine (one warp per row) ----
    {
        int nref = *refcnt;
        for (int f = warp; f < nref; f += 16) {
            int r = reflist[f];
            int c = cand[r * 8 + (lane >> 2)];           // candidate for this lane group
            int seg = (lane & 3) * 16;                   // 16 dims per lane
            const float4* x4 = reinterpret_cast<const float4*>(
                X + (size_t)(rowBase + r) * DIM + seg);
            const float4* e4 = reinterpret_cast<const float4*>(g_ET + c * DIM + seg);
            float s = 0.f;
            #pragma unroll
            for (int i = 0; i < 4; ++i) {
                float4 xv = x4[i];
                float4 ev = e4[i];
                s = fmaf(xv.x, ev.x, s);
                s = fmaf(xv.y, ev.y, s);
                s = fmaf(xv.z, ev.z, s);
                s = fmaf(xv.w, ev.w, s);
            }
            // sum within the 4-lane group
            s += __shfl_xor_sync(0xffffffffu, s, 1);
            s += __shfl_xor_sync(0xffffffffu, s, 2);
            float dist = fmaf(-2.f, s, enorm_s[c]);
            // min across 8 candidate groups (index tie-break)
            float bv = dist; int bi = c;
            #pragma unroll
            for (int off = 4; off <= 16; off <<= 1) {
                float ov = __shfl_xor_sync(0xffffffffu, bv, off);
                int   oi = __shfl_xor_sync(0xffffffffu, bi, off);
                if (ov < bv || (ov == bv && oi < bi)) { bv = ov; bi = oi; }
            }
            if (lane == 0) {
                rowcode[r] = bi;
                size_t p = IDX_OFF + (size_t)(rowBase + r);
                if (p < (size_t)out_size) out[p] = (float)bi;
            }
        }
    }

    // ---- rare full fp32 rescan (crowded near-ties), one warp per row ----
    {
        int nflag = *flagcnt;
        for (int f = warp; f < nflag; f += 16) {
            int r = flaglist[f];
            const float* xr = X + (size_t)(rowBase + r) * DIM;
            float4 acc4[4];
            #pragma unroll
            for (int j = 0; j < 4; ++j) acc4[j] = make_float4(0.f, 0.f, 0.f, 0.f);
            for (int d = 0; d < DIM; ++d) {
                float xd = xr[d];
                #pragma unroll
                for (int j = 0; j < 4; ++j) {
                    float4 ev = *reinterpret_cast<const float4*>(
                        E + (size_t)d * KCODES + j * 128 + lane * 4);
                    acc4[j].x = fmaf(xd, ev.x, acc4[j].x);
                    acc4[j].y = fmaf(xd, ev.y, acc4[j].y);
                    acc4[j].z = fmaf(xd, ev.z, acc4[j].z);
                    acc4[j].w = fmaf(xd, ev.w, acc4[j].w);
                }
            }
            float bv = CUDART_INF_F;
            int   bi = 0;
            #pragma unroll
            for (int j = 0; j < 4; ++j) {
                float dv[4] = {acc4[j].x, acc4[j].y, acc4[j].z, acc4[j].w};
                #pragma unroll
                for (int e = 0; e < 4; ++e) {
                    int   c = j * 128 + lane * 4 + e;
                    float v = fmaf(-2.f, dv[e], enorm_s[c]);
                    if (v < bv) { bv = v; bi = c; }
                }
            }
            #pragma unroll
            for (int st = 16; st > 0; st >>= 1) {
                float ov = __shfl_xor_sync(0xffffffffu, bv, st);
                int   oi = __shfl_xor_sync(0xffffffffu, bi, st);
                if (ov < bv || (ov == bv && oi < bi)) { bv = ov; bi = oi; }
            }
            if (lane == 0) {
                rowcode[r] = bi;
                size_t p = IDX_OFF + (size_t)(rowBase + r);
                if (p < (size_t)out_size) out[p] = (float)bi;
            }
        }
    }
    __syncthreads();

    // ---- gather quantized via transposed ET (coalesced), loss ----
    float lsum = 0.f;
    #pragma unroll 8
    for (int i = tid; i < ROWS_BLK * DIM; i += THREADS) {
        int r = i >> 6, d = i & 63;
        int code = rowcode[r];
        float qv = g_ET[code * DIM + d];
        float xv = X[(size_t)(rowBase + r) * DIM + d];
        out[(size_t)(rowBase + r) * DIM + d] = qv;
        float df = qv - xv;
        lsum = fmaf(df, df, lsum);
    }

    // ---- block loss reduction ----
    __syncthreads();
    float* red = reinterpret_cast<float*>(smem + OFF_RED);
    red[tid] = lsum;
    __syncthreads();
    #pragma unroll
    for (int s = THREADS / 2; s > 0; s >>= 1) {
        if (tid < s) red[tid] += red[tid + s];
        __syncthreads();
    }

    // ---- last-block deterministic final loss reduction ----
    __shared__ int islast;
    if (tid == 0) {
        g_partials[blockIdx.x] = red[0];
        __threadfence();
        int tk = atomicAdd(&g_done, 1);
        islast = (tk == NCTAS - 1) ? 1 : 0;
    }
    __syncthreads();
    if (islast) {
        volatile float* gp = g_partials;
        float s = (tid < NCTAS) ? gp[tid] : 0.f;
        red[tid] = s;
        __syncthreads();
        #pragma unroll
        for (int st = THREADS / 2; st > 0; st >>= 1) {
            if (tid < st) red[tid] += red[tid + st];
            __syncthreads();
        }
        if (tid == 0) {
            float loss = 1.25f * red[0] / (float)Q_ELEMS;
            if (LOSS_OFF < (size_t)out_size) out[LOSS_OFF] = loss;
            g_done = 0;                     // reset for next graph replay
        }
    }
}

// ---------------------------------------------------------------------------
extern "C" void kernel_launch(void* const* d_in, const int* in_sizes, int n_in,
                              void* d_out, int out_size) {
    const float* X;
    const float* E;
    if (in_sizes[0] == DIM * KCODES && in_sizes[1] != DIM * KCODES) {
        E = (const float*)d_in[0];
        X = (const float*)d_in[1];
    } else {
        X = (const float*)d_in[0];
        E = (const float*)d_in[1];
    }
    float* out = (float*)d_out;

    static bool attr_done = false;
    if (!attr_done) {
        cudaFuncSetAttribute(vq_kernel,
                             cudaFuncAttributeMaxDynamicSharedMemorySize, SMEM_TOTAL);
        attr_done = true;
    }

    vq_prep_kernel<<<64, 512>>>(E);
    vq_kernel<<<NCTAS, THREADS, SMEM_TOTAL>>>(X, E, out, out_size);
}